// round 13
// baseline (speedup 1.0000x reference)
#include <cuda_runtime.h>

// RSLDS forward-backward smoother, B=8 T=1024 N=64 K=8.
// Outputs: forward | backward | gamma1 | gamma2 (concatenated in d_out).
//
//   pass1: 8x8 transfer-matrix products. R13: Q mirrored in SMEM (stride-12
//          columns, conflict-free, broadcast LDS.128 gather) — crossbar slots
//          per step drop ~25 -> ~17 (shuffles can't dedup broadcasts; LDS can).
//   pass2: sequential scan over segments -> boundary vectors
//   fwbwgamma: fw recursion cached in SMEM, then bw recursion + emission.
//          R13: fw/bw/g1 written by ONE predicated STG (contiguous d_out
//          regions share the element offset) instead of three.

#define FULLMASK 0xffffffffu
constexpr int B_ = 8, T_ = 1024, N_ = 64, K_ = 8;
constexpr int C_ = B_ * N_;          // 512 chains
constexpr int L_ = 32, S_ = 32;      // segment length, count
constexpr int TN = T_ * N_;
constexpr long long BTNK = (long long)B_ * T_ * N_ * K_;
constexpr int BTNKi = (int)BTNK;     // 4,194,304 — fits int32

__device__ float g_Q  [C_ * S_ * 64];  // segment transfer matrices (linear)
__device__ float g_Vb [C_ * S_ * 8];   // fw boundaries (linear, rescaled)
__device__ float g_Rb [C_ * S_ * 8];   // bw boundaries (linear, rescaled)

__device__ __forceinline__ float ex2f(float x) {
    float y; asm("ex2.approx.ftz.f32 %0, %1;" : "=f"(y) : "f"(x)); return y;
}
__device__ __forceinline__ float lg2f(float x) {
    float y; asm("lg2.approx.f32 %0, %1;" : "=f"(y) : "f"(x)); return y;
}
__device__ __forceinline__ float rcpf(float x) {
    float y; asm("rcp.approx.ftz.f32 %0, %1;" : "=f"(y) : "f"(x)); return y;
}

#define L2E 1.4426950408889634f
#define LN2 0.6931471805599453f

// ---------------------------------------------------------------------------
// pass1: Q_s = M_te ... M_ts,  M_t[i,j] = exp(log_b_t[i] + log_a_t[i,j]).
// lane (i = lane>>2, q = lane&3) holds Q[i][2q], Q[i][2q+1] in regs; the warp
// mirrors Q in SMEM column-major with stride 12 (Qs[c*12 + l] = Q[l][c]).
// Per step: distinct float2 M load, 8 fixed-order row shuffles, 4 broadcast
// LDS.128 for Q columns, 2 conflict-free STS for the new Q.
// ---------------------------------------------------------------------------
__global__ void __launch_bounds__(128) pass1_kernel(
    const float* __restrict__ la, const float* __restrict__ lb)
{
    __shared__ float sQ[4][96];            // 8 cols x stride 12 per warp
    const int wl   = threadIdx.x >> 5;
    const int w    = blockIdx.x * 4 + wl;
    const int lane = threadIdx.x & 31;
    const int q    = lane & 3;
    const int i    = lane >> 2;
    const int gb   = lane & ~3;            // group base lane (= 4*i)
    const int c = w >> 5, s = w & 31;
    const int b = c >> 6, n = c & 63;
    const int tile0 = b * TN + n;
    float* Qs = sQ[wl];
    const int stc0 = 24 * q + i;           // smem slot of Q[i][2q]
    const int stc1 = 24 * q + 12 + i;      // smem slot of Q[i][2q+1]

    const int ts = (s == 0) ? 1 : s * L_;
    const int te = s * L_ + L_ - 1;
    const int cnt = te - ts;               // multiply steps: 30 or 31

    // mt[i][2q], mt[i][2q+1] = float2 at la[... + i*8 + 2q] -> float2 idx lane
    const float2* ap = (const float2*)la + (tile0 + ts * N_) * 32 + lane;
    const float*  bp = lb + (tile0 + ts * N_) * 8 + i;

    float Qx, Qy;
    {   // Q = M_ts (registers + smem mirror)
        float2 a2 = *ap;
        float  biL = (*bp) * L2E;
        Qx = ex2f(fmaf(a2.x, L2E, biL));
        Qy = ex2f(fmaf(a2.y, L2E, biL));
        ap += 32 * N_; bp += 8 * N_;
        Qs[stc0] = Qx;
        Qs[stc1] = Qy;
    }
    __syncwarp();

    // depth-2 prefetch buffers (cnt >= 30 always)
    float2 a2x = ap[0];        float bix = bp[0];
    float2 a2y = ap[32 * N_];  float biy = bp[8 * N_];
    ap += 64 * N_; bp += 16 * N_;

    int rcnt = 0;
    auto mstep = [&](float2 a2, float bi) {
        float biL = bi * L2E;
        float m0 = ex2f(fmaf(a2.x, L2E, biL));     // mt[i][2q]
        float m1 = ex2f(fmaf(a2.y, L2E, biL));     // mt[i][2q+1]
        // materialize row i of mt in l-order (8 fixed shuffles)
        float r0 = __shfl_sync(FULLMASK, m0, gb);
        float r1 = __shfl_sync(FULLMASK, m1, gb);
        float r2 = __shfl_sync(FULLMASK, m0, gb + 1);
        float r3 = __shfl_sync(FULLMASK, m1, gb + 1);
        float r4 = __shfl_sync(FULLMASK, m0, gb + 2);
        float r5 = __shfl_sync(FULLMASK, m1, gb + 2);
        float r6 = __shfl_sync(FULLMASK, m0, gb + 3);
        float r7 = __shfl_sync(FULLMASK, m1, gb + 3);
        // Q columns 2q, 2q+1 (broadcast within q-groups, conflict-free)
        float4 qa = *(const float4*)(Qs + 24 * q);        // Q[0..3][2q]
        float4 qb = *(const float4*)(Qs + 24 * q + 4);    // Q[4..7][2q]
        float4 qc = *(const float4*)(Qs + 24 * q + 12);   // Q[0..3][2q+1]
        float4 qd = *(const float4*)(Qs + 24 * q + 16);   // Q[4..7][2q+1]

        float nx = fmaf(r0, qa.x, fmaf(r1, qa.y, fmaf(r2, qa.z, fmaf(r3, qa.w,
                   fmaf(r4, qb.x, fmaf(r5, qb.y, fmaf(r6, qb.z, r7 * qb.w)))))));
        float ny = fmaf(r0, qc.x, fmaf(r1, qc.y, fmaf(r2, qc.z, fmaf(r3, qc.w,
                   fmaf(r4, qd.x, fmaf(r5, qd.y, fmaf(r6, qd.z, r7 * qd.w)))))));

        ++rcnt;
        if ((rcnt & 3) == 0 || rcnt == cnt) {      // rescale every 4 + final
            float m = fmaxf(nx, ny);
            m = fmaxf(m, __shfl_xor_sync(FULLMASK, m, 1));
            m = fmaxf(m, __shfl_xor_sync(FULLMASK, m, 2));
            m = fmaxf(m, __shfl_xor_sync(FULLMASK, m, 4));
            m = fmaxf(m, __shfl_xor_sync(FULLMASK, m, 8));
            m = fmaxf(m, __shfl_xor_sync(FULLMASK, m, 16));
            float inv = rcpf(m);
            nx *= inv; ny *= inv;
        }
        Qx = nx; Qy = ny;
        Qs[stc0] = nx;                              // mirror (conflict-free STS)
        Qs[stc1] = ny;
    };

    for (int u = 0; u + 2 <= cnt; u += 2) {
        float2 a = a2x; float bb = bix;
        if (u + 2 < cnt) { a2x = *ap; bix = *bp; ap += 32 * N_; bp += 8 * N_; }
        mstep(a, bb);
        a = a2y; bb = biy;
        if (u + 3 < cnt) { a2y = *ap; biy = *bp; ap += 32 * N_; bp += 8 * N_; }
        mstep(a, bb);
    }
    if (cnt & 1) mstep(a2x, bix);

    *(float2*)(g_Q + (size_t)(c * S_ + s) * 64 + lane * 2) = make_float2(Qx, Qy);
}

// ---------------------------------------------------------------------------
// pass2: sequential scan over segments. warp = (dir, chain).
// ---------------------------------------------------------------------------
__global__ void __launch_bounds__(128) pass2_kernel(
    const float* __restrict__ lb, const float* __restrict__ lz)
{
    const int w    = blockIdx.x * 4 + (threadIdx.x >> 5);
    const int lane = threadIdx.x & 31;
    const int q    = lane & 3;
    const int i    = lane >> 2;
    const bool is_bw = (w >= C_);
    const int c = is_bw ? w - C_ : w;
    const int b = c >> 6, n = c & 63;
    const int tile0 = b * TN + n;

    if (!is_bw) {
        float x = lz[n * 8 + i] + lb[tile0 * 8 + i];
        float m0 = x;
        m0 = fmaxf(m0, __shfl_xor_sync(FULLMASK, m0, 4));
        m0 = fmaxf(m0, __shfl_xor_sync(FULLMASK, m0, 8));
        m0 = fmaxf(m0, __shfl_xor_sync(FULLMASK, m0, 16));
        float vi = ex2f((x - m0) * L2E);       // v[i], replicated over q

        for (int s = 0; s <= 30; s++) {
            float2 Qr = *(const float2*)(g_Q + (size_t)(c * S_ + s) * 64 + lane * 2);
            float vx = __shfl_sync(FULLMASK, vi, 8 * q);
            float vy = __shfl_sync(FULLMASK, vi, 8 * q + 4);
            float p = fmaf(Qr.x, vx, Qr.y * vy);
            p += __shfl_xor_sync(FULLMASK, p, 1);
            p += __shfl_xor_sync(FULLMASK, p, 2);
            float m = p;
            m = fmaxf(m, __shfl_xor_sync(FULLMASK, m, 4));
            m = fmaxf(m, __shfl_xor_sync(FULLMASK, m, 8));
            m = fmaxf(m, __shfl_xor_sync(FULLMASK, m, 16));
            vi = p * rcpf(m);
            if (q == 0) g_Vb[(size_t)(c * S_ + s + 1) * 8 + i] = vi;
        }
    } else {
        float ri = 1.0f;
        for (int s = 31; s >= 1; s--) {
            float2 Qr = *(const float2*)(g_Q + (size_t)(c * S_ + s) * 64 + lane * 2);
            float pe = Qr.x * ri;
            float po = Qr.y * ri;
            pe += __shfl_xor_sync(FULLMASK, pe, 4);
            pe += __shfl_xor_sync(FULLMASK, pe, 8);
            pe += __shfl_xor_sync(FULLMASK, pe, 16);
            po += __shfl_xor_sync(FULLMASK, po, 4);
            po += __shfl_xor_sync(FULLMASK, po, 8);
            po += __shfl_xor_sync(FULLMASK, po, 16);
            float re = __shfl_sync(FULLMASK, pe, i >> 1);
            float ro = __shfl_sync(FULLMASK, po, i >> 1);
            float rn = (i & 1) ? ro : re;
            float m = fmaxf(pe, po);
            m = fmaxf(m, __shfl_xor_sync(FULLMASK, m, 1));
            m = fmaxf(m, __shfl_xor_sync(FULLMASK, m, 2));
            ri = rn * rcpf(m);
            if (q == 0) g_Rb[(size_t)(c * S_ + s) * 8 + i] = ri;
        }
    }
}

// ---------------------------------------------------------------------------
// fwbwgamma: forward recursion (alphas cached in SMEM, 1KB/warp), then
// backward recursion + all output emission in the same warp.
// fw/bw/g1 share element offset ob and live in contiguous d_out regions:
// ONE predicated STG with per-ii base offset replaces three.
// ---------------------------------------------------------------------------
__global__ void __launch_bounds__(128) fwbwgamma_kernel(
    const float* __restrict__ la, const float* __restrict__ lb,
    const float* __restrict__ lz,
    float* __restrict__ out,                // fw | bw | g1 base (= d_out)
    float* __restrict__ g2)
{
    __shared__ float sfw[4 * 264];          // 264-stride staggers banks per warp
    const int wl   = threadIdx.x >> 5;
    const int w    = blockIdx.x * 4 + wl;
    const int lane = threadIdx.x & 31;
    const int ii   = lane & 3;
    const int rr   = lane >> 2;
    const int c = w >> 5, s = w & 31;
    const int b = c >> 6, n = c & 63;
    const int tile0 = b * TN + n;
    const int sel0 = ii * 8, sel1 = ii * 8 + 4;
    const int sL = s * L_;
    const int te = sL + L_ - 1;
    float* fc = sfw + wl * 264;             // fwu cache: [tloc][rr]
    // per-ii output region: 0 -> bw, 1 -> fw, 2 -> g1 (3 inactive)
    const int ooff = (ii == 0) ? BTNKi : (ii == 2) ? 2 * BTNKi : 0;

    // ===================== forward sweep =====================
    {
        float prev;
        int t0;
        if (s == 0) {
            prev = (lz[n * 8 + rr] + lb[tile0 * 8 + rr]) * L2E;
            if (ii == 0) fc[rr] = prev;     // tloc 0
            t0 = 1;
        } else {
            prev = lg2f(g_Vb[(c * S_ + s) * 8 + rr]);
            t0 = sL;
        }
        const int cnt = te - t0 + 1;        // 31 or 32

        const float2* ap = (const float2*)la + (tile0 + t0 * N_) * 32 + lane;
        const float*  bp = lb + (tile0 + t0 * N_) * 8 + rr;
        float*        op = fc + (t0 - sL) * 8 + rr;

        float2 avx = ap[0];       float bvx = bp[0];
        float2 avy = ap[32 * N_]; float bvy = bp[8 * N_];
        ap += 64 * N_; bp += 16 * N_;

        auto fstep = [&](float2 av, float bv) {
            float p0 = __shfl_sync(FULLMASK, prev, sel0);
            float p1 = __shfl_sync(FULLMASK, prev, sel1);
            float u0 = __shfl_sync(FULLMASK, prev, 0);
            float e = ex2f(fmaf(av.x, L2E, p0 - u0))
                    + ex2f(fmaf(av.y, L2E, p1 - u0));
            e += __shfl_xor_sync(FULLMASK, e, 1);
            e += __shfl_xor_sync(FULLMASK, e, 2);
            float uu = fmaf(bv, L2E, lg2f(e));
            prev = uu;
            if (ii == 0) *op = uu;
            op += 8;
        };

        for (int u = 0; u + 2 <= cnt; u += 2) {
            float2 a = avx; float bb = bvx;
            if (u + 2 < cnt) { avx = *ap; bvx = *bp; ap += 32 * N_; bp += 8 * N_; }
            fstep(a, bb);
            a = avy; bb = bvy;
            if (u + 3 < cnt) { avy = *ap; bvy = *bp; ap += 32 * N_; bp += 8 * N_; }
            fstep(a, bb);
        }
        if (cnt & 1) fstep(avx, bvx);
    }
    __syncwarp();

    // ===================== backward + emission sweep =====================
    const int lnZ = lane | 3;               // same rr, ii=3 lane
    const bool top = (s == 31);

    float prev  = top ? 0.0f : lg2f(g_Rb[(c * S_ + s + 1) * 8 + rr]);
    float fprev = fc[31 * 8 + rr];          // fwu[te]

    const float*  cp  = la + (size_t)(tile0 + te * N_) * 64 + ii * 16 + rr;
    const float2* bp2 = (const float2*)lb + (tile0 + te * N_) * 4 + ii;
    const float*  fp  = fc + 30 * 8 + rr;   // fwu[te-1]
    int ob  = (tile0 + te * N_) * 8 + rr;   // fw/bw/g1 element offset
    int g2b = (tile0 + te * N_) * 64;       // gamma2 tile base

    // depth-2 prefetch (31 iterations always)
    float c0x = cp[0], c1x = cp[8];
    float2 bvx = bp2[0];
    float fcx = fp[0];
    float c0y = cp[-64 * N_], c1y = cp[-64 * N_ + 8];
    float2 bvy = bp2[-4 * N_];
    float fcy = fp[-8];
    cp -= 128 * N_; bp2 -= 8 * N_; fp -= 16;

    auto step = [&](float c0, float c1, float2 bv, float fcur, bool first) {
        // recursion core (beta_{t+1} -> beta_t)
        float p0 = __shfl_sync(FULLMASK, prev, sel0);
        float p1 = __shfl_sync(FULLMASK, prev, sel1);
        float u0 = __shfl_sync(FULLMASK, prev, 0);
        float a0 = fmaf(c0 + bv.x, L2E, p0 - u0);
        float a1 = fmaf(c1 + bv.y, L2E, p1 - u0);
        float e  = ex2f(a0) + ex2f(a1);
        e += __shfl_xor_sync(FULLMASK, e, 1);
        e += __shfl_xor_sync(FULLMASK, e, 2);   // e(rr) = sum over i

        // unified emission reduction for time t+1 (per-ii operand)
        float val = (ii == 0) ? prev
                  : (ii == 1) ? fprev
                  : (ii == 2) ? (fprev + prev) : fcur;
        float ee = ex2f(val);
        if (ii == 3) ee *= e;                   // gamma2 Z terms
        ee += __shfl_xor_sync(FULLMASK, ee, 4);
        ee += __shfl_xor_sync(FULLMASK, ee, 8);
        ee += __shfl_xor_sync(FULLMASK, ee, 16);
        float lgE = lg2f(ee);                   // per-ii normalizer
        float lgZ = __shfl_sync(FULLMASK, lgE, lnZ);

        float outv = (val - lgE) * LN2;
        if (ii == 0 && top && first) outv = 0.0f;   // beta_{T-1} raw zeros
        if (ii < 3) out[ooff + ob] = outv;          // ONE store: bw/fw/g1

        float tt2 = (fcur - lgZ) * LN2;
        g2[g2b + 16 * ii + rr]     = fmaf(a0, LN2, tt2);
        g2[g2b + 16 * ii + 8 + rr] = fmaf(a1, LN2, tt2);

        prev  = lg2f(e);
        fprev = fcur;
        ob -= 8 * N_; g2b -= 64 * N_;
    };

    for (int u = 0; u + 2 <= 31; u += 2) {
        {
            float c0 = c0x, c1 = c1x; float2 bv = bvx; float fcv = fcx;
            if (u + 2 < 31) {
                c0x = cp[0]; c1x = cp[8]; bvx = bp2[0]; fcx = fp[0];
                cp -= 64 * N_; bp2 -= 4 * N_; fp -= 8;
            }
            step(c0, c1, bv, fcv, u == 0);
        }
        {
            float c0 = c0y, c1 = c1y; float2 bv = bvy; float fcv = fcy;
            if (u + 3 < 31) {
                c0y = cp[0]; c1y = cp[8]; bvy = bp2[0]; fcy = fp[0];
                cp -= 64 * N_; bp2 -= 4 * N_; fp -= 8;
            }
            step(c0, c1, bv, fcv, false);
        }
    }
    step(c0x, c1x, bvx, fcx, false);           // iteration 30 (odd leftover)

    // ---- tail emission for time t = sL (prev = beta_{sL}, fprev = fwu[sL]) ----
    {
        float a0t = 0.f, a1t = 0.f, et = 1.0f, fct = 0.f;
        if (s != 0) {
            const float* cpe = la + (size_t)(tile0 + sL * N_) * 64 + ii * 16 + rr;
            float  c0 = cpe[0];
            float  c1 = cpe[8];
            float2 bv = *((const float2*)lb + (tile0 + sL * N_) * 4 + ii);
            fct = lg2f(g_Vb[(c * S_ + s) * 8 + rr]);     // fwu[sL-1] (shifted)
            float p0 = __shfl_sync(FULLMASK, prev, sel0);
            float p1 = __shfl_sync(FULLMASK, prev, sel1);
            float u0 = __shfl_sync(FULLMASK, prev, 0);
            a0t = fmaf(c0 + bv.x, L2E, p0 - u0);
            a1t = fmaf(c1 + bv.y, L2E, p1 - u0);
            et  = ex2f(a0t) + ex2f(a1t);
            et += __shfl_xor_sync(FULLMASK, et, 1);
            et += __shfl_xor_sync(FULLMASK, et, 2);
        }
        float val = (ii == 0) ? prev
                  : (ii == 1) ? fprev
                  : (ii == 2) ? (fprev + prev) : fct;
        float ee = ex2f(val);
        if (ii == 3) ee *= et;
        ee += __shfl_xor_sync(FULLMASK, ee, 4);
        ee += __shfl_xor_sync(FULLMASK, ee, 8);
        ee += __shfl_xor_sync(FULLMASK, ee, 16);
        float lgE = lg2f(ee);
        float lgZ = __shfl_sync(FULLMASK, lgE, lnZ);

        float outv = (val - lgE) * LN2;
        if (ii < 3) out[ooff + ob] = outv;          // ONE store: bw/fw/g1

        if (s == 0) {                               // gamma2[0] = zeros
            g2[g2b + 16 * ii + rr]     = 0.0f;
            g2[g2b + 16 * ii + 8 + rr] = 0.0f;
        } else {
            float tt2 = (fct - lgZ) * LN2;
            g2[g2b + 16 * ii + rr]     = fmaf(a0t, LN2, tt2);
            g2[g2b + 16 * ii + 8 + rr] = fmaf(a1t, LN2, tt2);
        }
    }
}

extern "C" void kernel_launch(void* const* d_in, const int* in_sizes, int n_in,
                              void* d_out, int out_size) {
    const float* la = (const float*)d_in[0];   // log_a  (B,T,N,K,K)
    const float* lb = (const float*)d_in[1];   // log_b  (B,T,N,K)
    const float* lz = (const float*)d_in[2];   // logprob_z1 (N,K)

    float* out = (float*)d_out;                // fw | bw | g1 | g2
    float* g2  = out + 3 * BTNK;

    pass1_kernel<<<(C_ * S_) / 4, 128>>>(la, lb);              // 16384 warps
    pass2_kernel<<<(2 * C_) / 4, 128>>>(lb, lz);               // 1024 warps
    fwbwgamma_kernel<<<(C_ * S_) / 4, 128>>>(la, lb, lz, out, g2);
}